// round 11
// baseline (speedup 1.0000x reference)
#include <cuda_runtime.h>
#include <cuda_fp16.h>
#include <cstdint>

// ---------------------------------------------------------------------------
// out[64,8192] = x[64,8192] @ dequant(B[1024,8192] int4-packed, s[64,8192])
// HMMA fp16 GEMM, fp32 accum. 256 threads, 8 warps: warp tile m64 x n32,
// 2 n-halves x 4-way k16-split. Cuts LDSM crossbar traffic 25% vs 32x32 tiles.
// 4-stage cp.async ring (A) + register prefetch dequant (B).
// ---------------------------------------------------------------------------

#define MDIM 64
#define KDIM 8192
#define NDIM 8192
#define NTILE 64
#define KTILE 64
#define NIT (KDIM / KTILE)   // 128 k-iterations
#define ASTRIDE 144          // smem row stride in bytes (64 fp16 + 16B pad)
#define NST 4
#define A_STG (64 * ASTRIDE)             // 9216
#define W_STG (64 * ASTRIDE)             // 9216
#define STG_BYTES (A_STG + W_STG)        // 18432
#define SMEM_TOTAL (NST * STG_BYTES)     // 73728

// fp16 x, pre-permuted: slot j of each 8-wide group holds x[8w + perm[j]],
// perm = {0,4,1,5,2,6,3,7} (the LOP3 magic-dequant output order).
__device__ __align__(16) __half g_xh[MDIM * KDIM];

// ---------------------------- helpers ---------------------------------------
__device__ __forceinline__ uint32_t smem_u32(const void* p) {
    uint32_t a;
    asm("{ .reg .u64 t; cvta.to.shared.u64 t, %1; cvt.u32.u64 %0, t; }"
        : "=r"(a) : "l"(p));
    return a;
}

union HU { uint32_t u; __half2 h; };
__device__ __forceinline__ __half2 u2h(uint32_t u) { HU c; c.u = u; return c.h; }
__device__ __forceinline__ uint32_t h2u(__half2 h) { HU c; c.h = h; return c.u; }

// magic dequant: 8 int4 nibbles -> 8 fp16 * scale, k-order {0,4,1,5,2,6,3,7}
__device__ __forceinline__ uint4 dq8(uint32_t w, __half2 s2) {
    const __half2 c1032 = __half2half2(__ushort_as_half((unsigned short)0x6408)); // 1032.0
    uint4 o;
    o.x = h2u(__hmul2(__hsub2(u2h((w         & 0x000F000Fu) | 0x64006400u), c1032), s2));
    o.y = h2u(__hmul2(__hsub2(u2h(((w >> 4)  & 0x000F000Fu) | 0x64006400u), c1032), s2));
    o.z = h2u(__hmul2(__hsub2(u2h(((w >> 8)  & 0x000F000Fu) | 0x64006400u), c1032), s2));
    o.w = h2u(__hmul2(__hsub2(u2h(((w >> 12) & 0x000F000Fu) | 0x64006400u), c1032), s2));
    return o;
}

#define LDSM4(r, addr)                                                          \
    asm volatile("ldmatrix.sync.aligned.m8n8.x4.shared.b16 {%0,%1,%2,%3}, [%4];"\
        : "=r"((r)[0]), "=r"((r)[1]), "=r"((r)[2]), "=r"((r)[3]) : "r"(addr))

#define MMA16816(c, a, bb0, bb1)                                                \
    asm volatile("mma.sync.aligned.m16n8k16.row.col.f32.f16.f16.f32 "           \
        "{%0,%1,%2,%3},{%4,%5,%6,%7},{%8,%9},{%0,%1,%2,%3};"                    \
        : "+f"((c)[0]), "+f"((c)[1]), "+f"((c)[2]), "+f"((c)[3])                \
        : "r"((a)[0]), "r"((a)[1]), "r"((a)[2]), "r"((a)[3]), "r"(bb0), "r"(bb1))

#define CP_ASYNC16(dst, src) \
    asm volatile("cp.async.cg.shared.global [%0], [%1], 16;" :: "r"(dst), "l"(src))
#define CP_COMMIT() asm volatile("cp.async.commit_group;" ::: "memory")
#define CP_WAIT2()  asm volatile("cp.async.wait_group 2;" ::: "memory")

// ------------------------------- prep: x -> fp16 permuted --------------------
__global__ void prep_kernel(const float* __restrict__ x) {
    int i = blockIdx.x * 256 + threadIdx.x;
    if (i < MDIM * KDIM) {
        int j = i & 7;
        int p = (0x73625140u >> (j * 4)) & 0xF;   // perm {0,4,1,5,2,6,3,7}
        g_xh[i] = __float2half_rn(x[(i & ~7) | p]);
    }
}

// ------------------------------- main kernel --------------------------------
__global__ void __launch_bounds__(256, 1)
machete_kernel(const int* __restrict__ gB, const float* __restrict__ gs,
               float* __restrict__ out) {
    extern __shared__ __align__(16) unsigned char dsm[];
    const uint32_t sb0 = smem_u32(dsm);

    const int t = threadIdx.x;
    const int lane = t & 31;
    const int wid = t >> 5;
    const int n0 = blockIdx.x * NTILE;

    // ---------------- load-phase mapping (all 256 threads) ----------------
    const int am = t >> 2, akq = t & 3;        // A: row(0..63), 32B chunk
    const int wn = t & 63, kw = t >> 6;        // W: n-row(0..63), words kw,kw+4
    const __half* aptr = g_xh + (size_t)am * KDIM + akq * 16;
    const int*    bptr = gB + (size_t)kw * NDIM + n0 + wn;
    const float*  sptr = gs + n0 + wn;
    const uint32_t sAoff = (uint32_t)(am * ASTRIDE + akq * 32);
    const uint32_t sWoff = (uint32_t)(wn * ASTRIDE + kw * 16);

    uint32_t rw[4][2];       // B prefetch: 4 iteration slots x 2 words
    float    rsv[4];

    auto ldgB = [&](int it) {
        const int sl = it & 3;
        const int* bp = bptr + (size_t)it * 8 * NDIM;
        rw[sl][0] = bp[0];
        rw[sl][1] = bp[(size_t)4 * NDIM];
        rsv[sl] = sptr[(size_t)(it >> 1) * NDIM];
    };
    auto stsW = [&](int it) {
        const int sl = it & 3;
        const __half2 s2 = __half2half2(__float2half_rn(rsv[sl]));
        unsigned char* wt = dsm + (it & (NST - 1)) * STG_BYTES + A_STG;
        *(uint4*)(wt + sWoff)      = dq8(rw[sl][0], s2);
        *(uint4*)(wt + sWoff + 64) = dq8(rw[sl][1], s2);
    };
    auto cpA = [&](int it) {
        const uint32_t dst = sb0 + (it & (NST - 1)) * STG_BYTES + sAoff;
        const __half* src = aptr + it * KTILE;
        CP_ASYNC16(dst, src);
        CP_ASYNC16(dst + 16, src + 8);
    };

    // ---------------- compute-phase mapping ----------------
    // 8 warps: nh = n-half (0,1), kq = k16 step within KTILE=64.
    // Warp tile: m64 x n32 -> 4 m-blocks x 4 n8-cols, 16 MMA/iter.
    const int nh = wid >> 2;
    const int kq = wid & 3;
    const int mat = lane >> 3, mr = lane & 7;
    const uint32_t aRowB = (uint32_t)(((mat & 1) * 8 + mr) * ASTRIDE
                                      + (mat >> 1) * 16 + kq * 32);
    const uint32_t bRowB = (uint32_t)((nh * 32 + (mat >> 1) * 8 + mr) * ASTRIDE
                                      + (mat & 1) * 16 + kq * 32);

    float acc[4][4][4];
    #pragma unroll
    for (int i = 0; i < 4; ++i)
        #pragma unroll
        for (int j = 0; j < 4; ++j)
            #pragma unroll
            for (int r = 0; r < 4; ++r) acc[i][j][r] = 0.f;

    auto compute = [&](int stg) {
        const uint32_t sAs = sb0 + stg * STG_BYTES;
        const uint32_t sWs = sAs + A_STG;
        uint32_t a[4][4], b[2][4];
        #pragma unroll
        for (int mb = 0; mb < 4; ++mb)
            LDSM4(a[mb], sAs + aRowB + mb * 16 * ASTRIDE);
        #pragma unroll
        for (int nb = 0; nb < 2; ++nb)
            LDSM4(b[nb], sWs + bRowB + nb * 16 * ASTRIDE);
        #pragma unroll
        for (int mb = 0; mb < 4; ++mb) {
            MMA16816(acc[mb][0], a[mb], b[0][0], b[0][1]);
            MMA16816(acc[mb][1], a[mb], b[0][2], b[0][3]);
            MMA16816(acc[mb][2], a[mb], b[1][0], b[1][1]);
            MMA16816(acc[mb][3], a[mb], b[1][2], b[1][3]);
        }
    };

    // ---------------- prologue ----------------
    {   // iter 0 W: load directly and store to stage 0
        const __half2 s2 = __half2half2(__float2half_rn(sptr[0]));
        *(uint4*)(dsm + A_STG + sWoff)      = dq8(bptr[0], s2);
        *(uint4*)(dsm + A_STG + sWoff + 64) = dq8(bptr[(size_t)4 * NDIM], s2);
    }
    ldgB(1);
    ldgB(2);
    cpA(0); CP_COMMIT();
    cpA(1); CP_COMMIT();

    // ---------------- main pipeline ----------------
    #pragma unroll 2
    for (int i = 0; i < NIT; ++i) {
        if (i + 1 < NIT) stsW(i + 1);      // dequant+store W for next iter
        if (i + 3 < NIT) ldgB(i + 3);      // B prefetch, 3 ahead
        if (i + 2 < NIT) cpA(i + 2);       // A prefetch, 2 ahead
        CP_COMMIT();
        CP_WAIT2();                        // A stage i arrived (this thread)
        __syncthreads();                   // stage i visible to all
        compute(i & (NST - 1));
    }
    __syncthreads();                       // protect smem reuse below

    // ---------------- 4-way k-split reduction + writeout ----------------
    // partials: 2 n-halves x 3 writers x 2048 floats = 48 KB in dsm
    float* red = (float*)dsm;
    if (kq != 0) {
        float* dst = red + (nh * 3 + (kq - 1)) * 2048 + lane * 4;
        #pragma unroll
        for (int mb = 0; mb < 4; ++mb)
            #pragma unroll
            for (int nc = 0; nc < 4; ++nc) {
                float4 v = make_float4(acc[mb][nc][0], acc[mb][nc][1],
                                       acc[mb][nc][2], acc[mb][nc][3]);
                *(float4*)(dst + (mb * 4 + nc) * 128) = v;
            }
    }
    __syncthreads();
    if (kq == 0) {
        const float* src = red + nh * 3 * 2048 + lane * 4;
        const int g = lane >> 2, cb = 2 * (lane & 3);
        #pragma unroll
        for (int mb = 0; mb < 4; ++mb)
            #pragma unroll
            for (int nc = 0; nc < 4; ++nc) {
                const int off = (mb * 4 + nc) * 128;
                float4 v0 = *(const float4*)(src + off);
                float4 v1 = *(const float4*)(src + 2048 + off);
                float4 v2 = *(const float4*)(src + 4096 + off);
                const int m = mb * 16 + g;
                const int c = n0 + nh * 32 + nc * 8 + cb;
                float2 lo = make_float2(acc[mb][nc][0] + v0.x + v1.x + v2.x,
                                        acc[mb][nc][1] + v0.y + v1.y + v2.y);
                float2 hi = make_float2(acc[mb][nc][2] + v0.z + v1.z + v2.z,
                                        acc[mb][nc][3] + v0.w + v1.w + v2.w);
                *(float2*)(out + (size_t)m * NDIM + c)       = lo;
                *(float2*)(out + (size_t)(m + 8) * NDIM + c) = hi;
            }
    }
}

// ------------------------------- launch -------------------------------------
extern "C" void kernel_launch(void* const* d_in, const int* in_sizes, int n_in,
                              void* d_out, int out_size) {
    const float* x = (const float*)d_in[0];
    const int* B   = (const int*)d_in[1];
    const float* s = (const float*)d_in[2];
    float* out = (float*)d_out;

    cudaFuncSetAttribute(machete_kernel,
                         cudaFuncAttributeMaxDynamicSharedMemorySize, SMEM_TOTAL);

    prep_kernel<<<(MDIM * KDIM + 255) / 256, 256>>>(x);
    machete_kernel<<<NDIM / NTILE, 256, SMEM_TOTAL>>>(B, s, out);
}

// round 12
// speedup vs baseline: 1.2309x; 1.2309x over previous
#include <cuda_runtime.h>
#include <cuda_fp16.h>
#include <cstdint>

// ---------------------------------------------------------------------------
// out[64,8192] = x[64,8192] @ dequant(B[1024,8192] int4-packed, s[64,8192])
// HMMA fp16 GEMM, fp32 accum. 512 threads, NTILE=64, KTILE=64.
// 8-stage ring in two halves; ONE __syncthreads + wait per 4 iterations.
// 16 warps: 4 tiles (32x32) x 4-way k16-split (the proven R5 mapping).
// ---------------------------------------------------------------------------

#define MDIM 64
#define KDIM 8192
#define NDIM 8192
#define NTILE 64
#define KTILE 64
#define NIT (KDIM / KTILE)   // 128 k-iterations
#define NH  (NIT / 4)        // 32 halves (4 iters each)
#define ASTRIDE 144          // smem row stride in bytes (64 fp16 + 16B pad)
#define NST 8
#define STG_BYTES (64 * ASTRIDE)              // 9216 per stage
#define SMEM_TOTAL (2 * NST * STG_BYTES)      // 147456: A ring then W ring

// fp16 x, pre-permuted: slot j of each 8-wide group holds x[8w + perm[j]],
// perm = {0,4,1,5,2,6,3,7} (the LOP3 magic-dequant output order).
__device__ __align__(16) __half g_xh[MDIM * KDIM];

// ---------------------------- helpers ---------------------------------------
__device__ __forceinline__ uint32_t smem_u32(const void* p) {
    uint32_t a;
    asm("{ .reg .u64 t; cvta.to.shared.u64 t, %1; cvt.u32.u64 %0, t; }"
        : "=r"(a) : "l"(p));
    return a;
}

union HU { uint32_t u; __half2 h; };
__device__ __forceinline__ __half2 u2h(uint32_t u) { HU c; c.u = u; return c.h; }
__device__ __forceinline__ uint32_t h2u(__half2 h) { HU c; c.h = h; return c.u; }

// magic dequant: 8 int4 nibbles -> 8 fp16 * scale, k-order {0,4,1,5,2,6,3,7}
__device__ __forceinline__ uint4 dq8(uint32_t w, __half2 s2) {
    const __half2 c1032 = __half2half2(__ushort_as_half((unsigned short)0x6408)); // 1032.0
    uint4 o;
    o.x = h2u(__hmul2(__hsub2(u2h((w         & 0x000F000Fu) | 0x64006400u), c1032), s2));
    o.y = h2u(__hmul2(__hsub2(u2h(((w >> 4)  & 0x000F000Fu) | 0x64006400u), c1032), s2));
    o.z = h2u(__hmul2(__hsub2(u2h(((w >> 8)  & 0x000F000Fu) | 0x64006400u), c1032), s2));
    o.w = h2u(__hmul2(__hsub2(u2h(((w >> 12) & 0x000F000Fu) | 0x64006400u), c1032), s2));
    return o;
}

#define LDSM4(r, addr)                                                          \
    asm volatile("ldmatrix.sync.aligned.m8n8.x4.shared.b16 {%0,%1,%2,%3}, [%4];"\
        : "=r"((r)[0]), "=r"((r)[1]), "=r"((r)[2]), "=r"((r)[3]) : "r"(addr))

#define MMA16816(c, a, bb0, bb1)                                                \
    asm volatile("mma.sync.aligned.m16n8k16.row.col.f32.f16.f16.f32 "           \
        "{%0,%1,%2,%3},{%4,%5,%6,%7},{%8,%9},{%0,%1,%2,%3};"                    \
        : "+f"((c)[0]), "+f"((c)[1]), "+f"((c)[2]), "+f"((c)[3])                \
        : "r"((a)[0]), "r"((a)[1]), "r"((a)[2]), "r"((a)[3]), "r"(bb0), "r"(bb1))

#define CP_ASYNC16(dst, src) \
    asm volatile("cp.async.cg.shared.global [%0], [%1], 16;" :: "r"(dst), "l"(src))
#define CP_COMMIT() asm volatile("cp.async.commit_group;" ::: "memory")
#define CP_WAIT0()  asm volatile("cp.async.wait_group 0;" ::: "memory")

// ------------------------------- prep: x -> fp16 permuted --------------------
__global__ void prep_kernel(const float* __restrict__ x) {
    int i = blockIdx.x * 256 + threadIdx.x;
    if (i < MDIM * KDIM) {
        int j = i & 7;
        int p = (0x73625140u >> (j * 4)) & 0xF;   // perm {0,4,1,5,2,6,3,7}
        g_xh[i] = __float2half_rn(x[(i & ~7) | p]);
    }
}

// ------------------------------- main kernel --------------------------------
__global__ void __launch_bounds__(512, 1)
machete_kernel(const int* __restrict__ gB, const float* __restrict__ gs,
               float* __restrict__ out) {
    extern __shared__ __align__(16) unsigned char dsm[];
    unsigned char* sA = dsm;                       // NST stages of A
    unsigned char* sW = dsm + NST * STG_BYTES;     // NST stages of W
    const uint32_t sAb0 = smem_u32(sA);
    const uint32_t sWb0 = smem_u32(sW);

    const int t = threadIdx.x;
    const int lane = t & 31;
    const int wid = t >> 5;
    const int n0 = blockIdx.x * NTILE;

    // ---------------- load-phase mapping (all 512 threads) ----------------
    const int am = t >> 3, akq = t & 7;        // A: row, 16B chunk
    const int wn = t & 63, kw = t >> 6;        // W: n-row, word index 0..7
    const __half* aptr = g_xh + (size_t)am * KDIM + akq * 8;
    const int*    bptr = gB + (size_t)kw * NDIM + n0 + wn;
    const float*  sptr = gs + n0 + wn;
    const uint32_t sAoff = (uint32_t)(am * ASTRIDE + akq * 16);
    const uint32_t sWoff = (uint32_t)(wn * ASTRIDE + kw * 16);

    uint32_t rw[8];          // B prefetch slots (2 halves in flight)
    float    rsv[8];

    auto ldgB = [&](int it) {
        const int sl = it & 7;
        rw[sl] = bptr[(size_t)it * 8 * NDIM];
        rsv[sl] = sptr[(size_t)(it >> 1) * NDIM];
    };
    auto stsW = [&](int it) {
        const int sl = it & 7;
        const __half2 s2 = __half2half2(__float2half_rn(rsv[sl]));
        unsigned char* wt = sW + (it & (NST - 1)) * STG_BYTES;
        *(uint4*)(wt + sWoff) = dq8(rw[sl], s2);
    };
    auto cpA = [&](int it) {
        const uint32_t dst = sAb0 + (it & (NST - 1)) * STG_BYTES + sAoff;
        CP_ASYNC16(dst, aptr + it * KTILE);
    };

    // ---------------- compute-phase mapping (R5 proven) ----------------
    // 4 output tiles of 32x32 (2m x 2n), 4 warps per tile split by k16 step.
    const int tile = wid >> 2;
    const int kq   = wid & 3;
    const int tm = (tile >> 1) * 32;
    const int tn = (tile & 1) * 32;
    const int mat = lane >> 3, mr = lane & 7;
    const uint32_t aRow = (uint32_t)((tm + (mat & 1) * 8 + mr) * ASTRIDE + (mat >> 1) * 16 + kq * 32);
    const uint32_t bRow = (uint32_t)((tn + (mat >> 1) * 8 + mr) * ASTRIDE + (mat & 1) * 16 + kq * 32);

    float acc[2][4][4];
    #pragma unroll
    for (int i = 0; i < 2; ++i)
        #pragma unroll
        for (int j = 0; j < 4; ++j)
            #pragma unroll
            for (int r = 0; r < 4; ++r) acc[i][j][r] = 0.f;

    auto compute = [&](int stg) {
        const uint32_t sAs = sAb0 + stg * STG_BYTES;
        const uint32_t sWs = sWb0 + stg * STG_BYTES;
        uint32_t a0[4], a1[4], b0[4], b1[4];
        LDSM4(a0, sAs + aRow);
        LDSM4(a1, sAs + aRow + 16 * ASTRIDE);
        LDSM4(b0, sWs + bRow);
        LDSM4(b1, sWs + bRow + 16 * ASTRIDE);
        MMA16816(acc[0][0], a0, b0[0], b0[1]);
        MMA16816(acc[0][1], a0, b0[2], b0[3]);
        MMA16816(acc[0][2], a0, b1[0], b1[1]);
        MMA16816(acc[0][3], a0, b1[2], b1[3]);
        MMA16816(acc[1][0], a1, b0[0], b0[1]);
        MMA16816(acc[1][1], a1, b0[2], b0[3]);
        MMA16816(acc[1][2], a1, b1[0], b1[1]);
        MMA16816(acc[1][3], a1, b1[2], b1[3]);
    };

    // ---------------- prologue: half 0 in place, half 1 staged ----------------
    #pragma unroll
    for (int it = 0; it < 4; ++it) {   // W stages 0-3: direct LDG + dequant
        const __half2 s2 = __half2half2(__float2half_rn(sptr[(size_t)(it >> 1) * NDIM]));
        unsigned char* wt = sW + it * STG_BYTES;
        *(uint4*)(wt + sWoff) = dq8(bptr[(size_t)it * 8 * NDIM], s2);
    }
    #pragma unroll
    for (int it = 4; it < 8; ++it) ldgB(it);   // regs for half 1's stsW
    #pragma unroll
    for (int it = 0; it < 4; ++it) cpA(it);    // A stages 0-3
    CP_COMMIT();
    CP_WAIT0();
    __syncthreads();

    // ---------------- main pipeline: one barrier per 4 iterations ----------------
    #pragma unroll 1
    for (int H = 0; H < NH; ++H) {
        const int i0 = H * 4;
        if (H + 2 < NH) {                      // B regs for half H+2
            #pragma unroll
            for (int j = 0; j < 4; ++j) ldgB(i0 + 8 + j);
        }
        if (H + 1 < NH) {                      // A + W stages for half H+1
            #pragma unroll
            for (int j = 0; j < 4; ++j) cpA(i0 + 4 + j);
            CP_COMMIT();
            #pragma unroll
            for (int j = 0; j < 4; ++j) stsW(i0 + 4 + j);
        }
        #pragma unroll
        for (int j = 0; j < 4; ++j) compute((i0 + j) & (NST - 1));
        CP_WAIT0();                            // next half's A landed
        __syncthreads();                       // next half visible to all
    }

    // ---------------- 4-way k-split reduction + writeout ----------------
    // partials: 4 tiles x 3 writers x 1024 floats = 48 KB in dsm
    float* red = (float*)dsm;
    if (kq != 0) {
        float* dst = red + (tile * 3 + (kq - 1)) * 1024 + lane * 4;
        #pragma unroll
        for (int ms = 0; ms < 2; ++ms)
            #pragma unroll
            for (int ns = 0; ns < 4; ++ns) {
                float4 v = make_float4(acc[ms][ns][0], acc[ms][ns][1],
                                       acc[ms][ns][2], acc[ms][ns][3]);
                *(float4*)(dst + (ms * 4 + ns) * 128) = v;
            }
    }
    __syncthreads();
    if (kq == 0) {
        const float* src = red + tile * 3 * 1024 + lane * 4;
        const int g = lane >> 2, cb = 2 * (lane & 3);
        #pragma unroll
        for (int ms = 0; ms < 2; ++ms)
            #pragma unroll
            for (int ns = 0; ns < 4; ++ns) {
                const int off = (ms * 4 + ns) * 128;
                float4 v0 = *(const float4*)(src + off);
                float4 v1 = *(const float4*)(src + 1024 + off);
                float4 v2 = *(const float4*)(src + 2048 + off);
                const int m = tm + ms * 16 + g;
                const int c = n0 + tn + ns * 8 + cb;
                float2 lo = make_float2(acc[ms][ns][0] + v0.x + v1.x + v2.x,
                                        acc[ms][ns][1] + v0.y + v1.y + v2.y);
                float2 hi = make_float2(acc[ms][ns][2] + v0.z + v1.z + v2.z,
                                        acc[ms][ns][3] + v0.w + v1.w + v2.w);
                *(float2*)(out + (size_t)m * NDIM + c)       = lo;
                *(float2*)(out + (size_t)(m + 8) * NDIM + c) = hi;
            }
    }
}

// ------------------------------- launch -------------------------------------
extern "C" void kernel_launch(void* const* d_in, const int* in_sizes, int n_in,
                              void* d_out, int out_size) {
    const float* x = (const float*)d_in[0];
    const int* B   = (const int*)d_in[1];
    const float* s = (const float*)d_in[2];
    float* out = (float*)d_out;

    cudaFuncSetAttribute(machete_kernel,
                         cudaFuncAttributeMaxDynamicSharedMemorySize, SMEM_TOTAL);

    prep_kernel<<<(MDIM * KDIM + 255) / 256, 256>>>(x);
    machete_kernel<<<NDIM / NTILE, 512, SMEM_TOTAL>>>(B, s, out);
}

// round 13
// speedup vs baseline: 1.6015x; 1.3011x over previous
#include <cuda_runtime.h>
#include <cuda_fp16.h>
#include <cstdint>

// ---------------------------------------------------------------------------
// out[64,8192] = x[64,8192] @ dequant(B[1024,8192] int4-packed, s[64,8192])
// Split-K=2 HMMA fp16 GEMM: grid (128 n-tiles x 2 k-halves), 256 thr/CTA,
// 2 CTAs/SM. Each CTA: 64 iters, 4-stage cp.async ring (A) + register
// prefetch dequant (B). k-half 1 -> partial buffer, reduce kernel adds.
// ---------------------------------------------------------------------------

#define MDIM 64
#define KDIM 8192
#define NDIM 8192
#define NTILE 64
#define KTILE 64
#define NIT (KDIM / KTILE / 2)   // 64 iters per k-half
#define ASTRIDE 144              // smem row stride (64 fp16 + 16B pad)
#define NST 4
#define STG_BYTES (64 * ASTRIDE)             // 9216 per stage
#define SMEM_TOTAL (2 * NST * STG_BYTES)     // 73728 -> 2 CTAs/SM

// fp16 x, pre-permuted: slot j of each 8-wide group holds x[8w + perm[j]],
// perm = {0,4,1,5,2,6,3,7} (the LOP3 magic-dequant output order).
__device__ __align__(16) __half g_xh[MDIM * KDIM];
// split-K partial for k-half 1
__device__ __align__(16) float g_part[MDIM * NDIM];

// ---------------------------- helpers ---------------------------------------
__device__ __forceinline__ uint32_t smem_u32(const void* p) {
    uint32_t a;
    asm("{ .reg .u64 t; cvta.to.shared.u64 t, %1; cvt.u32.u64 %0, t; }"
        : "=r"(a) : "l"(p));
    return a;
}

union HU { uint32_t u; __half2 h; };
__device__ __forceinline__ __half2 u2h(uint32_t u) { HU c; c.u = u; return c.h; }
__device__ __forceinline__ uint32_t h2u(__half2 h) { HU c; c.h = h; return c.u; }

// magic dequant: 8 int4 nibbles -> 8 fp16 * scale, k-order {0,4,1,5,2,6,3,7}
__device__ __forceinline__ uint4 dq8(uint32_t w, __half2 s2) {
    const __half2 c1032 = __half2half2(__ushort_as_half((unsigned short)0x6408)); // 1032.0
    uint4 o;
    o.x = h2u(__hmul2(__hsub2(u2h((w         & 0x000F000Fu) | 0x64006400u), c1032), s2));
    o.y = h2u(__hmul2(__hsub2(u2h(((w >> 4)  & 0x000F000Fu) | 0x64006400u), c1032), s2));
    o.z = h2u(__hmul2(__hsub2(u2h(((w >> 8)  & 0x000F000Fu) | 0x64006400u), c1032), s2));
    o.w = h2u(__hmul2(__hsub2(u2h(((w >> 12) & 0x000F000Fu) | 0x64006400u), c1032), s2));
    return o;
}

#define LDSM4(r, addr)                                                          \
    asm volatile("ldmatrix.sync.aligned.m8n8.x4.shared.b16 {%0,%1,%2,%3}, [%4];"\
        : "=r"((r)[0]), "=r"((r)[1]), "=r"((r)[2]), "=r"((r)[3]) : "r"(addr))

#define MMA16816(c, a, bb0, bb1)                                                \
    asm volatile("mma.sync.aligned.m16n8k16.row.col.f32.f16.f16.f32 "           \
        "{%0,%1,%2,%3},{%4,%5,%6,%7},{%8,%9},{%0,%1,%2,%3};"                    \
        : "+f"((c)[0]), "+f"((c)[1]), "+f"((c)[2]), "+f"((c)[3])                \
        : "r"((a)[0]), "r"((a)[1]), "r"((a)[2]), "r"((a)[3]), "r"(bb0), "r"(bb1))

#define CP_ASYNC16(dst, src) \
    asm volatile("cp.async.cg.shared.global [%0], [%1], 16;" :: "r"(dst), "l"(src))
#define CP_COMMIT() asm volatile("cp.async.commit_group;" ::: "memory")
#define CP_WAIT2()  asm volatile("cp.async.wait_group 2;" ::: "memory")

// ------------------------------- prep: x -> fp16 permuted --------------------
__global__ void prep_kernel(const float* __restrict__ x) {
    int i = blockIdx.x * 256 + threadIdx.x;
    if (i < MDIM * KDIM) {
        int j = i & 7;
        int p = (0x73625140u >> (j * 4)) & 0xF;   // perm {0,4,1,5,2,6,3,7}
        g_xh[i] = __float2half_rn(x[(i & ~7) | p]);
    }
}

// ------------------------------- reduce: out += part -------------------------
__global__ void reduce_kernel(float* __restrict__ out) {
    int i = blockIdx.x * 256 + threadIdx.x;
    float4 a = *(const float4*)(out + i * 4);
    float4 b = *(const float4*)(g_part + i * 4);
    a.x += b.x; a.y += b.y; a.z += b.z; a.w += b.w;
    *(float4*)(out + i * 4) = a;
}

// ------------------------------- main kernel --------------------------------
__global__ void __launch_bounds__(256, 2)
machete_kernel(const int* __restrict__ gB, const float* __restrict__ gs,
               float* __restrict__ out) {
    extern __shared__ __align__(16) unsigned char dsm[];
    unsigned char* sA = dsm;                       // NST stages of A
    unsigned char* sW = dsm + NST * STG_BYTES;     // NST stages of W
    const uint32_t sAb0 = smem_u32(sA);
    const uint32_t sWb0 = smem_u32(sW);

    const int t = threadIdx.x;
    const int lane = t & 31;
    const int wid = t >> 5;
    const int n0 = blockIdx.x * NTILE;
    const int kp = blockIdx.y;                 // k-half 0 / 1

    // ---------------- load-phase mapping (all 256 threads) ----------------
    const int am = t >> 2, akq = t & 3;        // A: row, 32B chunk
    const int wn = t & 63, kw2 = t >> 6;       // W: n-row, word-pair index
    const __half* aptr = g_xh + (size_t)am * KDIM + (size_t)kp * (KDIM / 2) + akq * 16;
    const int*    bptr = gB + ((size_t)kp * 512 + 2 * kw2) * NDIM + n0 + wn;
    const float*  sptr = gs + (size_t)kp * 32 * NDIM + n0 + wn;
    const uint32_t sAoff = (uint32_t)(am * ASTRIDE + akq * 32);
    const uint32_t sWoff = (uint32_t)(wn * ASTRIDE + kw2 * 32);

    uint32_t rw[2][2];       // B prefetch slots (iter parity)
    float    rsv[2];

    auto ldgB = [&](int it) {
        const int* bp = bptr + (size_t)it * 8 * NDIM;
        const int sl = it & 1;
        rw[sl][0] = bp[0];
        rw[sl][1] = bp[NDIM];
        rsv[sl] = sptr[(size_t)(it >> 1) * NDIM];
    };
    auto stsW = [&](int it) {
        const int sl = it & 1;
        const __half2 s2 = __half2half2(__float2half_rn(rsv[sl]));
        unsigned char* wt = sW + (it & (NST - 1)) * STG_BYTES;
        *(uint4*)(wt + sWoff)      = dq8(rw[sl][0], s2);
        *(uint4*)(wt + sWoff + 16) = dq8(rw[sl][1], s2);
    };
    auto cpA = [&](int it) {
        const uint32_t dst = sAb0 + (it & (NST - 1)) * STG_BYTES + sAoff;
        const __half* src = aptr + it * KTILE;
        CP_ASYNC16(dst, src);
        CP_ASYNC16(dst + 16, src + 8);
    };

    // ---------------- compute-phase mapping ----------------
    // 4 output tiles of 32x32 (2m x 2n), 2 warps per tile split by k-step.
    const int tile  = wid >> 1;
    const int khalf = wid & 1;
    const int tm = (tile >> 1) * 32;
    const int tn = (tile & 1) * 32;
    const int mat = lane >> 3, mr = lane & 7;
    const uint32_t aRow = (uint32_t)((tm + (mat & 1) * 8 + mr) * ASTRIDE + (mat >> 1) * 16);
    const uint32_t bRow = (uint32_t)((tn + (mat >> 1) * 8 + mr) * ASTRIDE + (mat & 1) * 16);

    float acc[2][4][4];
    #pragma unroll
    for (int i = 0; i < 2; ++i)
        #pragma unroll
        for (int j = 0; j < 4; ++j)
            #pragma unroll
            for (int r = 0; r < 4; ++r) acc[i][j][r] = 0.f;

    auto compute = [&](int stg) {
        const uint32_t sAs = sAb0 + stg * STG_BYTES;
        const uint32_t sWs = sWb0 + stg * STG_BYTES;
        #pragma unroll
        for (int s = 0; s < 2; ++s) {
            const int ks = khalf + 2 * s;
            uint32_t a0[4], a1[4], b0[4], b1[4];
            LDSM4(a0, sAs + aRow + ks * 32);
            LDSM4(a1, sAs + aRow + 16 * ASTRIDE + ks * 32);
            LDSM4(b0, sWs + bRow + ks * 32);
            LDSM4(b1, sWs + bRow + 16 * ASTRIDE + ks * 32);
            MMA16816(acc[0][0], a0, b0[0], b0[1]);
            MMA16816(acc[0][1], a0, b0[2], b0[3]);
            MMA16816(acc[0][2], a0, b1[0], b1[1]);
            MMA16816(acc[0][3], a0, b1[2], b1[3]);
            MMA16816(acc[1][0], a1, b0[0], b0[1]);
            MMA16816(acc[1][1], a1, b0[2], b0[3]);
            MMA16816(acc[1][2], a1, b1[0], b1[1]);
            MMA16816(acc[1][3], a1, b1[2], b1[3]);
        }
    };

    // ---------------- prologue ----------------
    {   // iter 0 W: load directly and store to stage 0
        const __half2 s2 = __half2half2(__float2half_rn(sptr[0]));
        *(uint4*)(sW + sWoff)      = dq8(bptr[0], s2);
        *(uint4*)(sW + sWoff + 16) = dq8(bptr[NDIM], s2);
    }
    ldgB(1);            // slot 1
    ldgB(2);            // slot 0
    cpA(0); CP_COMMIT();
    cpA(1); CP_COMMIT();

    // ---------------- main pipeline ----------------
    #pragma unroll 4
    for (int i = 0; i < NIT; ++i) {
        if (i + 1 < NIT) stsW(i + 1);      // dequant+store W for next iter
        if (i + 3 < NIT) ldgB(i + 3);      // B prefetch, 3 ahead
        if (i + 2 < NIT) cpA(i + 2);       // A prefetch, 2 ahead
        CP_COMMIT();
        CP_WAIT2();                        // A stage i arrived (this thread)
        __syncthreads();                   // stage i visible to all
        compute(i & (NST - 1));
    }
    __syncthreads();                       // protect smem reuse below

    // ---------------- k-half reduction + writeout ----------------
    float* obase = (kp == 0) ? out : g_part;
    float* red = (float*)dsm;              // 4 tiles * 1024 floats = 16 KB
    if (khalf == 1) {
        float* dst = red + tile * 1024 + lane * 4;
        #pragma unroll
        for (int ms = 0; ms < 2; ++ms)
            #pragma unroll
            for (int ns = 0; ns < 4; ++ns) {
                float4 v = make_float4(acc[ms][ns][0], acc[ms][ns][1],
                                       acc[ms][ns][2], acc[ms][ns][3]);
                *(float4*)(dst + (ms * 4 + ns) * 128) = v;
            }
    }
    __syncthreads();
    if (khalf == 0) {
        const float* src = red + tile * 1024 + lane * 4;
        const int g = lane >> 2, cb = 2 * (lane & 3);
        #pragma unroll
        for (int ms = 0; ms < 2; ++ms)
            #pragma unroll
            for (int ns = 0; ns < 4; ++ns) {
                float4 v = *(const float4*)(src + (ms * 4 + ns) * 128);
                const int m = tm + ms * 16 + g;
                const int c = n0 + tn + ns * 8 + cb;
                float2 lo = make_float2(acc[ms][ns][0] + v.x, acc[ms][ns][1] + v.y);
                float2 hi = make_float2(acc[ms][ns][2] + v.z, acc[ms][ns][3] + v.w);
                *(float2*)(obase + (size_t)m * NDIM + c)       = lo;
                *(float2*)(obase + (size_t)(m + 8) * NDIM + c) = hi;
            }
    }
}

// ------------------------------- launch -------------------------------------
extern "C" void kernel_launch(void* const* d_in, const int* in_sizes, int n_in,
                              void* d_out, int out_size) {
    const float* x = (const float*)d_in[0];
    const int* B   = (const int*)d_in[1];
    const float* s = (const float*)d_in[2];
    float* out = (float*)d_out;

    cudaFuncSetAttribute(machete_kernel,
                         cudaFuncAttributeMaxDynamicSharedMemorySize, SMEM_TOTAL);

    prep_kernel<<<(MDIM * KDIM + 255) / 256, 256>>>(x);
    dim3 grid(NDIM / NTILE, 2);
    machete_kernel<<<grid, 256, SMEM_TOTAL>>>(B, s, out);
    reduce_kernel<<<(MDIM * NDIM / 4 + 255) / 256, 256>>>(out);
}